// round 8
// baseline (speedup 1.0000x reference)
#include <cuda_runtime.h>
#include <cuda_fp16.h>
#include <cstdint>

#define N_SEND 12288
#define N_REC  49152
#define NE     196608
#define DD     256
#define K1     512
#define MTOT   98304

// ---------------- static device scratch ----------------
__device__ __half d_Acc[(size_t)MTOT * K1];    // [m][512] fp16
__device__ __half d_Amid[(size_t)MTOT * DD];   // [m][256] fp16
__device__ __half d_B1[DD * K1];               // [n][512] fp16
__device__ __half d_B2[DD * DD];               // [n][256] fp16
__device__ float  d_bc[DD];
__device__ int    d_offs[N_REC + 1];

// ---------------- gelu ----------------
__device__ __forceinline__ float gelu_mufu(float v) {
    float u = 0.7978845608028654f * fmaf(0.044715f * v, v * v, v);
    float t;
    asm("ex2.approx.f32 %0, %1;" : "=f"(t) : "f"(-2.8853900817779268f * u));
    float r;
    asm("rcp.approx.f32 %0, %1;" : "=f"(r) : "f"(1.0f + t));
    return v * r;
}
__device__ __forceinline__ float gelu_poly(float v) {
    float u = 0.7978845608028654f * fmaf(0.044715f * v, v * v, v);
    float u2 = u * u;
    float p = fmaf(u2, -0.008863235530f, 0.021869488536f);
    p = fmaf(u2, p, -0.053968253968f);
    p = fmaf(u2, p, 0.133333333333f);
    p = fmaf(u2, p, -0.333333333333f);
    float th = fmaf(u2 * u, p, u);
    float g = fmaf(0.5f * v, th, 0.5f * v);
    if (__builtin_expect(fabsf(u) > 0.65f, 0)) g = gelu_mufu(v);
    return g;
}
__device__ __forceinline__ void ldsm4(uint32_t* r, uint32_t addr) {
    asm volatile("ldmatrix.sync.aligned.m8n8.x4.shared.b16 {%0,%1,%2,%3}, [%4];"
                 : "=r"(r[0]), "=r"(r[1]), "=r"(r[2]), "=r"(r[3]) : "r"(addr));
}
__device__ __forceinline__ void mma16816(float* c, const uint32_t* a, const uint32_t* b) {
    asm volatile("mma.sync.aligned.m16n8k16.row.col.f32.f16.f16.f32 "
                 "{%0,%1,%2,%3}, {%4,%5,%6,%7}, {%8,%9}, {%0,%1,%2,%3};"
                 : "+f"(c[0]), "+f"(c[1]), "+f"(c[2]), "+f"(c[3])
                 : "r"(a[0]), "r"(a[1]), "r"(a[2]), "r"(a[3]), "r"(b[0]), "r"(b[1]));
}
#define CP_ASYNC16(s, g) asm volatile("cp.async.cg.shared.global [%0], [%1], 16;" :: "r"(s), "l"(g))
#define CP_COMMIT()      asm volatile("cp.async.commit_group;" ::: "memory")
#define CP_WAIT(n)       asm volatile("cp.async.wait_group %0;" :: "n"(n) : "memory")

// ---------------- prep: build d_B1 = [Wl1[:256]; We2@Wl1[256:]]^T and d_bc directly ----------------
__global__ void prep_b1_kernel(const float* __restrict__ Wl1,
                               const float* __restrict__ We2,
                               const float* __restrict__ be2) {
    int n = threadIdx.x;          // output col of W1cat (0..255)
    int k = blockIdx.x;           // 0..511 -> B1 row-k; 512 -> bc
    if (k < 256) {
        d_B1[(size_t)n * K1 + k] = __float2half_rn(Wl1[k * DD + n]);
    } else if (k < 512) {
        int j = k - 256;
        float acc = 0.f;
        #pragma unroll 4
        for (int kk = 0; kk < 256; kk++)
            acc += We2[j * 256 + kk] * Wl1[(256 + kk) * DD + n];
        d_B1[(size_t)n * K1 + k] = __float2half_rn(acc);
    } else {
        float acc = 0.f;
        #pragma unroll 4
        for (int kk = 0; kk < 256; kk++)
            acc += be2[kk] * Wl1[(256 + kk) * DD + n];
        d_bc[n] = acc;
    }
}
__global__ void pack_b2(const float* __restrict__ Wl2) {
    int n = threadIdx.x, k = blockIdx.x;
    d_B2[(size_t)n * DD + k] = __float2half_rn(Wl2[k * DD + n]);
}

// ---------------- segment offsets ----------------
__global__ void seg_offs_kernel(const int* __restrict__ idx_rec) {
    int e = blockIdx.x * 256 + threadIdx.x;
    if (e >= NE) return;
    int cur = idx_rec[e];
    int nxt = (e + 1 < NE) ? idx_rec[e + 1] : N_REC;
    for (int r = cur + 1; r <= nxt; r++) d_offs[r] = e + 1;
    if (e == 0) {
        for (int r = 0; r <= cur; r++) d_offs[r] = 0;
    }
}

// ---------------- fused gather + edge-MLP + segment sum (4 edge slots) ----------------
__global__ __launch_bounds__(256) void edge_kernel(const float* __restrict__ x,
                            const float* __restrict__ edge_attr,
                            const int*  __restrict__ idx_send,
                            const float* __restrict__ We1,
                            const float* __restrict__ be1) {
    __shared__ float4 sA0[4][64], sA1[4][64], sAG[4][64];
    const int r = blockIdx.x;
    const int tid = threadIdx.x;
    const int slot = tid >> 6, c = tid & 63;
    const int start = d_offs[r], end = d_offs[r + 1];

    const float4 w0 = *(const float4*)&We1[c * 4];
    const float4 w1 = *(const float4*)&We1[256 + c * 4];
    const float4 w2 = *(const float4*)&We1[512 + c * 4];
    const float4 w3 = *(const float4*)&We1[768 + c * 4];
    const float4 b0 = *(const float4*)&be1[c * 4];

    const float4* x4 = (const float4*)x;
    float4 a0 = make_float4(0.f, 0.f, 0.f, 0.f);
    float4 a1 = a0, aG = a0;

    for (int e = start + slot; e < end; e += 4) {
        int s = idx_send[e];
        float4 ea = reinterpret_cast<const float4*>(edge_attr)[e];
        float tx = b0.x + ea.x * w0.x + ea.y * w1.x + ea.z * w2.x + ea.w * w3.x;
        float ty = b0.y + ea.x * w0.y + ea.y * w1.y + ea.z * w2.y + ea.w * w3.y;
        float tz = b0.z + ea.x * w0.z + ea.y * w1.z + ea.z * w2.z + ea.w * w3.z;
        float tw = b0.w + ea.x * w0.w + ea.y * w1.w + ea.z * w2.w + ea.w * w3.w;
        aG.x += gelu_poly(tx); aG.y += gelu_poly(ty);
        aG.z += gelu_poly(tz); aG.w += gelu_poly(tw);
        float4 xv = x4[(size_t)s * 64 + c];
        a0.x += xv.x; a0.y += xv.y; a0.z += xv.z; a0.w += xv.w;
        float4 xv2 = x4[((size_t)N_SEND + s) * 64 + c];
        a1.x += xv2.x; a1.y += xv2.y; a1.z += xv2.z; a1.w += xv2.w;
    }
    sA0[slot][c] = a0; sA1[slot][c] = a1; sAG[slot][c] = aG;
    __syncthreads();

    if (tid < 192) {
        int grp = tid >> 6, cc = tid & 63;
        const float4* s4 = (grp == 0) ? sA0[0] : (grp == 1) ? sA1[0] : sAG[0];
        float4 v0 = s4[cc], v1 = s4[64 + cc], v2 = s4[128 + cc], v3 = s4[192 + cc];
        float4 v;
        v.x = v0.x + v1.x + v2.x + v3.x;
        v.y = v0.y + v1.y + v2.y + v3.y;
        v.z = v0.z + v1.z + v2.z + v3.z;
        v.w = v0.w + v1.w + v2.w + v3.w;
        __half2 h01 = __floats2half2_rn(v.x, v.y);
        __half2 h23 = __floats2half2_rn(v.z, v.w);
        uint2 u = make_uint2(*(uint32_t*)&h01, *(uint32_t*)&h23);
        size_t m0 = (size_t)r * K1;
        size_t m1 = ((size_t)N_REC + r) * K1;
        if (grp == 0) {
            *(uint2*)&d_Acc[m0 + cc * 4] = u;
        } else if (grp == 1) {
            *(uint2*)&d_Acc[m1 + cc * 4] = u;
        } else {
            *(uint2*)&d_Acc[m0 + DD + cc * 4] = u;
            *(uint2*)&d_Acc[m1 + DD + cc * 4] = u;
        }
    }
}

// ---------------- HMMA GEMM: 128x128 CTA tile, K-chunks of 64, single fp16 ----------------
#define SM_BIAS 0u
#define SM_BC   1024u
#define SM_CNT  2048u
#define SM_BUF  4096u
#define BUF_SZ  32768u
#define SMEM_TOTAL (4096 + 3 * 32768)

template <int KD>
__device__ __forceinline__ void load_tile(uint32_t sdst, const __half* __restrict__ g, int tid) {
    #pragma unroll
    for (int i = 0; i < 4; i++) {
        int lin = i * 256 + tid;
        int r = lin >> 3, c = lin & 7;
        uint32_t sa = sdst + (uint32_t)r * 128u + (uint32_t)((c ^ (r & 7)) << 4);
        const __half* ga = g + (size_t)r * KD + c * 8;
        CP_ASYNC16(sa, ga);
    }
}

template <int KD, int EPI>
__global__ __launch_bounds__(256, 1) void gemm_hmma(const float* __restrict__ bias,
                                                    float* __restrict__ outp) {
    constexpr int KC = KD / 64;
    extern __shared__ char smem[];
    const uint32_t sb = (uint32_t)__cvta_generic_to_shared(smem);
    const int tid = threadIdx.x;
    const int tileN = blockIdx.x, tileM = blockIdx.y;
    const int wid = tid >> 5, lane = tid & 31;
    const int wm = (wid >> 2) * 64, wn = (wid & 3) * 32;

    const __half* Ag = EPI ? d_Acc : d_Amid;
    const __half* Bg = EPI ? d_B1 : d_B2;

    if (tid < 128) {
        ((float*)(smem + SM_BIAS))[tid] = bias[tileN * 128 + tid];
        if (EPI) {
            ((float*)(smem + SM_BC))[tid] = d_bc[tileN * 128 + tid];
            int R = tileM * 128 + tid;
            int rr = (R >= N_REC) ? R - N_REC : R;
            ((float*)(smem + SM_CNT))[tid] = (float)(d_offs[rr + 1] - d_offs[rr]);
        }
    }

    const size_t Abase = (size_t)tileM * 128 * KD;
    const size_t Bbase = (size_t)tileN * 128 * KD;

    #define LOAD_CHUNK(c, buf) do {                                         \
        uint32_t s_ = sb + SM_BUF + (uint32_t)(buf) * BUF_SZ;               \
        load_tile<KD>(s_,          Ag + Abase + (c) * 64, tid);             \
        load_tile<KD>(s_ + 16384u, Bg + Bbase + (c) * 64, tid);             \
        CP_COMMIT();                                                        \
    } while (0)

    LOAD_CHUNK(0, 0);
    LOAD_CHUNK(1, 1);
    if (KC > 2) LOAD_CHUNK(2, 2);

    const int sub = lane >> 3, rr8 = lane & 7;
    const int Ar0 = wm + ((sub & 1) << 3) + rr8;
    const int aSel = sub >> 1;
    const int Ar7 = Ar0 & 7;
    const int Bn0 = wn + ((sub >> 1) << 3) + rr8;
    const int bSel = sub & 1;
    const int Bn7 = Bn0 & 7;

    float acc[64];
    #pragma unroll
    for (int i = 0; i < 64; i++) acc[i] = 0.f;

    #pragma unroll
    for (int c = 0; c < KC; c++) {
        if (KC - 1 - c >= 2)      { CP_WAIT(2); }
        else if (KC - 1 - c == 1) { CP_WAIT(1); }
        else                      { CP_WAIT(0); }
        __syncthreads();

        const uint32_t sB0 = sb + SM_BUF + (uint32_t)(c % 3) * BUF_SZ;
        const uint32_t sA = sB0, sB = sB0 + 16384u;

        #pragma unroll
        for (int kk = 0; kk < 4; kk++) {
            uint32_t bh[8];
            #pragma unroll
            for (int p = 0; p < 2; p++) {
                int cB = kk * 2 + bSel;
                uint32_t boff = (uint32_t)(Bn0 + p * 16) * 128u + (uint32_t)((cB ^ Bn7) << 4);
                ldsm4(&bh[p * 4], sB + boff);
            }
            #pragma unroll
            for (int t = 0; t < 4; t++) {
                int cA = kk * 2 + aSel;
                uint32_t aoff = (uint32_t)(Ar0 + t * 16) * 128u + (uint32_t)((cA ^ Ar7) << 4);
                uint32_t ah[4];
                ldsm4(ah, sA + aoff);
                #pragma unroll
                for (int n = 0; n < 4; n++) {
                    mma16816(&acc[(t * 4 + n) * 4], ah, &bh[(n >> 1) * 4 + (n & 1) * 2]);
                }
            }
        }
        __syncthreads();
        if (c + 3 < KC) LOAD_CHUNK(c + 3, c % 3);
    }
    #undef LOAD_CHUNK

    const int gid = lane >> 2, qid = lane & 3;
    const float* sbias = (const float*)(smem + SM_BIAS);
    const float* sbc   = (const float*)(smem + SM_BC);
    const float* scnt  = (const float*)(smem + SM_CNT);

    #pragma unroll
    for (int t = 0; t < 4; t++) {
        #pragma unroll
        for (int n = 0; n < 4; n++) {
            float* a4 = &acc[(t * 4 + n) * 4];
            int rl = wm + t * 16 + gid;
            int cl = wn + n * 8 + qid * 2;
            int Rl = tileM * 128 + rl;
            int C  = tileN * 128 + cl;
            float b0 = sbias[cl], b1 = sbias[cl + 1];
            if (EPI) {
                float bc0 = sbc[cl], bc1 = sbc[cl + 1];
                float cf0 = scnt[rl], cf1 = scnt[rl + 8];
                float v00 = gelu_mufu(a4[0] + b0 + cf0 * bc0);
                float v01 = gelu_mufu(a4[1] + b1 + cf0 * bc1);
                float v10 = gelu_mufu(a4[2] + b0 + cf1 * bc0);
                float v11 = gelu_mufu(a4[3] + b1 + cf1 * bc1);
                *(__half2*)&d_Amid[(size_t)Rl * DD + C] =
                    __halves2half2(__float2half_rn(v00), __float2half_rn(v01));
                *(__half2*)&d_Amid[(size_t)(Rl + 8) * DD + C] =
                    __halves2half2(__float2half_rn(v10), __float2half_rn(v11));
            } else {
                float2 v0 = make_float2(a4[0] + b0, a4[1] + b1);
                float2 v1 = make_float2(a4[2] + b0, a4[3] + b1);
                *(float2*)&outp[(size_t)Rl * DD + C] = v0;
                *(float2*)&outp[(size_t)(Rl + 8) * DD + C] = v1;
            }
        }
    }
}

// ---------------- launch ----------------
extern "C" void kernel_launch(void* const* d_in, const int* in_sizes, int n_in,
                              void* d_out, int out_size) {
    const float* x         = (const float*)d_in[0];
    const float* edge_attr = (const float*)d_in[1];
    const int*   idx_send  = (const int*)d_in[2];
    const int*   idx_rec   = (const int*)d_in[3];
    const float* We1       = (const float*)d_in[4];
    const float* be1       = (const float*)d_in[5];
    const float* We2       = (const float*)d_in[6];
    const float* be2       = (const float*)d_in[7];
    const float* Wl1       = (const float*)d_in[8];
    const float* bl1       = (const float*)d_in[9];
    const float* Wl2       = (const float*)d_in[10];
    const float* bl2       = (const float*)d_in[11];
    float* out = (float*)d_out;

    static bool attr_done = false;
    if (!attr_done) {
        cudaFuncSetAttribute(gemm_hmma<K1, 1>, cudaFuncAttributeMaxDynamicSharedMemorySize, SMEM_TOTAL);
        cudaFuncSetAttribute(gemm_hmma<DD, 0>, cudaFuncAttributeMaxDynamicSharedMemorySize, SMEM_TOTAL);
        attr_done = true;
    }

    prep_b1_kernel<<<513, 256>>>(Wl1, We2, be2);
    pack_b2<<<DD, 256>>>(Wl2);
    seg_offs_kernel<<<(NE + 255) / 256, 256>>>(idx_rec);
    edge_kernel<<<N_REC, 256>>>(x, edge_attr, idx_send, We1, be1);

    gemm_hmma<K1, 1><<<dim3(2, 768), 256, SMEM_TOTAL>>>(bl1, nullptr);
    gemm_hmma<DD, 0><<<dim3(2, 768), 256, SMEM_TOTAL>>>(bl2, out);
}

// round 9
// speedup vs baseline: 1.0634x; 1.0634x over previous
#include <cuda_runtime.h>
#include <cuda_fp16.h>
#include <cstdint>

#define N_SEND 12288
#define N_REC  49152
#define NE     196608
#define DD     256
#define MTOT   98304
#define NROWX  24576   // 2 * N_SEND

// ---------------- static device scratch ----------------
__device__ __half d_Xs[(size_t)NROWX * 512];   // x split: [m][0:256]=hi, [256:512]=lo
__device__ __half d_Y[(size_t)NROWX * DD];     // Y = x @ W1a   (fp16)
__device__ __half d_Yacc[(size_t)MTOT * DD];   // segsum(Y[idx_send]) per batch
__device__ __half d_AccG[(size_t)N_REC * DD];  // segsum(gelu(edge mlp))
__device__ __half d_Amid[(size_t)MTOT * DD];   // gelu(H) fp16
__device__ __half d_B1Y[DD * 512];             // W1a^T duplicated (for split-K GEMM_Y)
__device__ __half d_Bg[DD * DD];               // (We2 @ Wl1[256:])^T
__device__ __half d_B2[DD * DD];               // Wl2^T
__device__ float  d_bc[DD];
__device__ int    d_offs[N_REC + 1];

// ---------------- gelu ----------------
__device__ __forceinline__ float gelu_mufu(float v) {
    float u = 0.7978845608028654f * fmaf(0.044715f * v, v * v, v);
    float t;
    asm("ex2.approx.f32 %0, %1;" : "=f"(t) : "f"(-2.8853900817779268f * u));
    float r;
    asm("rcp.approx.f32 %0, %1;" : "=f"(r) : "f"(1.0f + t));
    return v * r;
}
__device__ __forceinline__ float gelu_poly(float v) {
    float u = 0.7978845608028654f * fmaf(0.044715f * v, v * v, v);
    float u2 = u * u;
    float p = fmaf(u2, -0.008863235530f, 0.021869488536f);
    p = fmaf(u2, p, -0.053968253968f);
    p = fmaf(u2, p, 0.133333333333f);
    p = fmaf(u2, p, -0.333333333333f);
    float th = fmaf(u2 * u, p, u);
    float g = fmaf(0.5f * v, th, 0.5f * v);
    if (__builtin_expect(fabsf(u) > 0.65f, 0)) g = gelu_mufu(v);
    return g;
}
__device__ __forceinline__ void ldsm4(uint32_t* r, uint32_t addr) {
    asm volatile("ldmatrix.sync.aligned.m8n8.x4.shared.b16 {%0,%1,%2,%3}, [%4];"
                 : "=r"(r[0]), "=r"(r[1]), "=r"(r[2]), "=r"(r[3]) : "r"(addr));
}
__device__ __forceinline__ void mma16816(float* c, const uint32_t* a, const uint32_t* b) {
    asm volatile("mma.sync.aligned.m16n8k16.row.col.f32.f16.f16.f32 "
                 "{%0,%1,%2,%3}, {%4,%5,%6,%7}, {%8,%9}, {%0,%1,%2,%3};"
                 : "+f"(c[0]), "+f"(c[1]), "+f"(c[2]), "+f"(c[3])
                 : "r"(a[0]), "r"(a[1]), "r"(a[2]), "r"(a[3]), "r"(b[0]), "r"(b[1]));
}
#define CP_ASYNC16(s, g) asm volatile("cp.async.cg.shared.global [%0], [%1], 16;" :: "r"(s), "l"(g))
#define CP_COMMIT()      asm volatile("cp.async.commit_group;" ::: "memory")
#define CP_WAIT(n)       asm volatile("cp.async.wait_group %0;" :: "n"(n) : "memory")

// ---------------- prep kernels ----------------
// B1Y[n][k] = Wl1[k & 255][n]  (W1a transposed, duplicated for hi|lo split-K)
__global__ void prep_b1y(const float* __restrict__ Wl1) {
    int n = threadIdx.x, k = blockIdx.x;       // k: 0..511
    d_B1Y[(size_t)n * 512 + k] = __float2half_rn(Wl1[(k & 255) * DD + n]);
}
// Bg[n][j] = (We2 @ Wl1[256:])[j][n];  bc = be2 @ Wl1[256:]
__global__ void prep_bg(const float* __restrict__ Wl1,
                        const float* __restrict__ We2,
                        const float* __restrict__ be2) {
    int n = threadIdx.x, j = blockIdx.x;
    if (j < 256) {
        float acc = 0.f;
        #pragma unroll 4
        for (int kk = 0; kk < 256; kk++)
            acc += We2[j * 256 + kk] * Wl1[(256 + kk) * DD + n];
        d_Bg[(size_t)n * DD + j] = __float2half_rn(acc);
    } else {
        float acc = 0.f;
        #pragma unroll 4
        for (int kk = 0; kk < 256; kk++)
            acc += be2[kk] * Wl1[(256 + kk) * DD + n];
        d_bc[n] = acc;
    }
}
__global__ void pack_b2(const float* __restrict__ Wl2) {
    int n = threadIdx.x, k = blockIdx.x;
    d_B2[(size_t)n * DD + k] = __float2half_rn(Wl2[k * DD + n]);
}
// split x into hi/lo halves of d_Xs rows
__global__ void pack_x(const float* __restrict__ x) {
    int m = blockIdx.x, c = threadIdx.x;
    float v = x[(size_t)m * DD + c];
    __half h = __float2half_rn(v);
    __half l = __float2half_rn(v - __half2float(h));
    d_Xs[(size_t)m * 512 + c] = h;
    d_Xs[(size_t)m * 512 + 256 + c] = l;
}

// ---------------- segment offsets ----------------
__global__ void seg_offs_kernel(const int* __restrict__ idx_rec) {
    int e = blockIdx.x * 256 + threadIdx.x;
    if (e >= NE) return;
    int cur = idx_rec[e];
    int nxt = (e + 1 < NE) ? idx_rec[e + 1] : N_REC;
    for (int r = cur + 1; r <= nxt; r++) d_offs[r] = e + 1;
    if (e == 0) {
        for (int r = 0; r <= cur; r++) d_offs[r] = 0;
    }
}

// ---------------- fused gather(Y) + edge-MLP + segment sum ----------------
__global__ __launch_bounds__(256) void edge_kernel(const float* __restrict__ edge_attr,
                            const int*  __restrict__ idx_send,
                            const float* __restrict__ We1,
                            const float* __restrict__ be1) {
    const int r = blockIdx.x;
    const int d = threadIdx.x;
    const int start = d_offs[r], end = d_offs[r + 1];

    const float w0 = We1[d], w1 = We1[256 + d], w2 = We1[512 + d], w3 = We1[768 + d];
    const float b0 = be1[d];
    const __half* Y0 = d_Y;
    const __half* Y1 = d_Y + (size_t)N_SEND * DD;

    float aG = 0.f, a0 = 0.f, a1 = 0.f;
    if (start < end) {
        int s = idx_send[start];
        float4 ea = reinterpret_cast<const float4*>(edge_attr)[start];
        for (int e = start; e < end; e++) {
            int s_cur = s;
            float4 ea_cur = ea;
            if (e + 1 < end) {
                s = idx_send[e + 1];
                ea = reinterpret_cast<const float4*>(edge_attr)[e + 1];
            }
            float t = b0 + ea_cur.x * w0 + ea_cur.y * w1 + ea_cur.z * w2 + ea_cur.w * w3;
            aG += gelu_poly(t);
            a0 += __half2float(Y0[(size_t)s_cur * DD + d]);
            a1 += __half2float(Y1[(size_t)s_cur * DD + d]);
        }
    }
    d_Yacc[(size_t)r * DD + d]             = __float2half_rn(a0);
    d_Yacc[((size_t)N_REC + r) * DD + d]   = __float2half_rn(a1);
    d_AccG[(size_t)r * DD + d]             = __float2half_rn(aG);
}

// ---------------- HMMA GEMM: 128x128 CTA tile, K-chunks of 64 ----------------
// MODE 2: d_Xs @ B1Y -> d_Y (fp16, no bias)         [KD=512, M=24576]
// MODE 3: d_AccG @ Bg; epi adds yacc/bias/cnt*bc, gelu -> d_Amid both batches [KD=256, M=49152]
// MODE 0: d_Amid @ B2 + bl2 -> out (fp32)            [KD=256, M=98304]
#define SM_BIAS 0u
#define SM_BC   1024u
#define SM_CNT  2048u
#define SM_BUF  4096u
#define BUF_SZ  32768u
#define SMEM_TOTAL (4096 + 3 * 32768)

template <int KD>
__device__ __forceinline__ void load_tile(uint32_t sdst, const __half* __restrict__ g, int tid) {
    #pragma unroll
    for (int i = 0; i < 4; i++) {
        int lin = i * 256 + tid;
        int r = lin >> 3, c = lin & 7;
        uint32_t sa = sdst + (uint32_t)r * 128u + (uint32_t)((c ^ (r & 7)) << 4);
        CP_ASYNC16(sa, g + (size_t)r * KD + c * 8);
    }
}

template <int KD, int MODE>
__global__ __launch_bounds__(256, 1) void gemm_hmma(const float* __restrict__ bias,
                                                    float* __restrict__ outp) {
    constexpr int KC = KD / 64;
    extern __shared__ char smem[];
    const uint32_t sb = (uint32_t)__cvta_generic_to_shared(smem);
    const int tid = threadIdx.x;
    const int tileN = blockIdx.x, tileM = blockIdx.y;
    const int wid = tid >> 5, lane = tid & 31;
    const int wm = (wid >> 2) * 64, wn = (wid & 3) * 32;

    const __half* Ag = (MODE == 3) ? d_AccG : ((MODE == 2) ? d_Xs : d_Amid);
    const __half* Bg = (MODE == 3) ? d_Bg   : ((MODE == 2) ? d_B1Y : d_B2);

    if (MODE != 2 && tid < 128) {
        ((float*)(smem + SM_BIAS))[tid] = bias[tileN * 128 + tid];
        if (MODE == 3) {
            ((float*)(smem + SM_BC))[tid] = d_bc[tileN * 128 + tid];
            int R = tileM * 128 + tid;
            ((float*)(smem + SM_CNT))[tid] = (float)(d_offs[R + 1] - d_offs[R]);
        }
    }

    const size_t Abase = (size_t)tileM * 128 * KD;
    const size_t Bbase = (size_t)tileN * 128 * KD;

    #define LOAD_CHUNK(c, buf) do {                                         \
        uint32_t s_ = sb + SM_BUF + (uint32_t)(buf) * BUF_SZ;               \
        load_tile<KD>(s_,          Ag + Abase + (c) * 64, tid);             \
        load_tile<KD>(s_ + 16384u, Bg + Bbase + (c) * 64, tid);             \
        CP_COMMIT();                                                        \
    } while (0)

    LOAD_CHUNK(0, 0);
    LOAD_CHUNK(1, 1);
    if (KC > 2) LOAD_CHUNK(2, 2);

    const int sub = lane >> 3, rr8 = lane & 7;
    const int Ar0 = wm + ((sub & 1) << 3) + rr8;
    const int aSel = sub >> 1;
    const int Ar7 = Ar0 & 7;
    const int Bn0 = wn + ((sub >> 1) << 3) + rr8;
    const int bSel = sub & 1;
    const int Bn7 = Bn0 & 7;

    float acc[64];
    #pragma unroll
    for (int i = 0; i < 64; i++) acc[i] = 0.f;

    #pragma unroll
    for (int c = 0; c < KC; c++) {
        if (KC - 1 - c >= 2)      { CP_WAIT(2); }
        else if (KC - 1 - c == 1) { CP_WAIT(1); }
        else                      { CP_WAIT(0); }
        __syncthreads();

        const uint32_t sB0 = sb + SM_BUF + (uint32_t)(c % 3) * BUF_SZ;
        const uint32_t sA = sB0, sB = sB0 + 16384u;

        #pragma unroll
        for (int kk = 0; kk < 4; kk++) {
            uint32_t bh[8];
            #pragma unroll
            for (int p = 0; p < 2; p++) {
                int cB = kk * 2 + bSel;
                uint32_t boff = (uint32_t)(Bn0 + p * 16) * 128u + (uint32_t)((cB ^ Bn7) << 4);
                ldsm4(&bh[p * 4], sB + boff);
            }
            #pragma unroll
            for (int t = 0; t < 4; t++) {
                int cA = kk * 2 + aSel;
                uint32_t aoff = (uint32_t)(Ar0 + t * 16) * 128u + (uint32_t)((cA ^ Ar7) << 4);
                uint32_t ah[4];
                ldsm4(ah, sA + aoff);
                #pragma unroll
                for (int n = 0; n < 4; n++) {
                    mma16816(&acc[(t * 4 + n) * 4], ah, &bh[(n >> 1) * 4 + (n & 1) * 2]);
                }
            }
        }
        __syncthreads();
        if (c + 3 < KC) LOAD_CHUNK(c + 3, c % 3);
    }
    #undef LOAD_CHUNK

    const int gid = lane >> 2, qid = lane & 3;
    const float* sbias = (const float*)(smem + SM_BIAS);
    const float* sbc   = (const float*)(smem + SM_BC);
    const float* scnt  = (const float*)(smem + SM_CNT);

    #pragma unroll
    for (int t = 0; t < 4; t++) {
        #pragma unroll
        for (int n = 0; n < 4; n++) {
            float* a4 = &acc[(t * 4 + n) * 4];
            int rl = wm + t * 16 + gid;
            int cl = wn + n * 8 + qid * 2;
            size_t Rg = (size_t)tileM * 128 + rl;
            int C  = tileN * 128 + cl;
            if (MODE == 2) {
                *(__half2*)&d_Y[Rg * DD + C] = __floats2half2_rn(a4[0], a4[1]);
                *(__half2*)&d_Y[(Rg + 8) * DD + C] = __floats2half2_rn(a4[2], a4[3]);
            } else if (MODE == 3) {
                float b0 = sbias[cl] , b1 = sbias[cl + 1];
                float bc0 = sbc[cl], bc1 = sbc[cl + 1];
                float cf0 = scnt[rl], cf1 = scnt[rl + 8];
                float s00 = a4[0] + b0 + cf0 * bc0, s01 = a4[1] + b1 + cf0 * bc1;
                float s10 = a4[2] + b0 + cf1 * bc0, s11 = a4[3] + b1 + cf1 * bc1;
                __half2 y00 = *(const __half2*)&d_Yacc[Rg * DD + C];
                __half2 y01 = *(const __half2*)&d_Yacc[(Rg + 8) * DD + C];
                __half2 y10 = *(const __half2*)&d_Yacc[((size_t)N_REC + Rg) * DD + C];
                __half2 y11 = *(const __half2*)&d_Yacc[((size_t)N_REC + Rg + 8) * DD + C];
                *(__half2*)&d_Amid[Rg * DD + C] = __floats2half2_rn(
                    gelu_mufu(s00 + __low2float(y00)), gelu_mufu(s01 + __high2float(y00)));
                *(__half2*)&d_Amid[(Rg + 8) * DD + C] = __floats2half2_rn(
                    gelu_mufu(s10 + __low2float(y01)), gelu_mufu(s11 + __high2float(y01)));
                *(__half2*)&d_Amid[((size_t)N_REC + Rg) * DD + C] = __floats2half2_rn(
                    gelu_mufu(s00 + __low2float(y10)), gelu_mufu(s01 + __high2float(y10)));
                *(__half2*)&d_Amid[((size_t)N_REC + Rg + 8) * DD + C] = __floats2half2_rn(
                    gelu_mufu(s10 + __low2float(y11)), gelu_mufu(s11 + __high2float(y11)));
            } else {
                float b0 = sbias[cl], b1 = sbias[cl + 1];
                *(float2*)&outp[Rg * DD + C] = make_float2(a4[0] + b0, a4[1] + b1);
                *(float2*)&outp[(Rg + 8) * DD + C] = make_float2(a4[2] + b0, a4[3] + b1);
            }
        }
    }
}

// ---------------- launch ----------------
extern "C" void kernel_launch(void* const* d_in, const int* in_sizes, int n_in,
                              void* d_out, int out_size) {
    const float* x         = (const float*)d_in[0];
    const float* edge_attr = (const float*)d_in[1];
    const int*   idx_send  = (const int*)d_in[2];
    const int*   idx_rec   = (const int*)d_in[3];
    const float* We1       = (const float*)d_in[4];
    const float* be1       = (const float*)d_in[5];
    const float* We2       = (const float*)d_in[6];
    const float* be2       = (const float*)d_in[7];
    const float* Wl1       = (const float*)d_in[8];
    const float* bl1       = (const float*)d_in[9];
    const float* Wl2       = (const float*)d_in[10];
    const float* bl2       = (const float*)d_in[11];
    float* out = (float*)d_out;

    static bool attr_done = false;
    if (!attr_done) {
        cudaFuncSetAttribute(gemm_hmma<512, 2>, cudaFuncAttributeMaxDynamicSharedMemorySize, SMEM_TOTAL);
        cudaFuncSetAttribute(gemm_hmma<256, 3>, cudaFuncAttributeMaxDynamicSharedMemorySize, SMEM_TOTAL);
        cudaFuncSetAttribute(gemm_hmma<256, 0>, cudaFuncAttributeMaxDynamicSharedMemorySize, SMEM_TOTAL);
        attr_done = true;
    }

    prep_b1y<<<512, 256>>>(Wl1);
    prep_bg<<<257, 256>>>(Wl1, We2, be2);
    pack_b2<<<DD, 256>>>(Wl2);
    pack_x<<<NROWX, 256>>>(x);
    seg_offs_kernel<<<(NE + 255) / 256, 256>>>(idx_rec);

    gemm_hmma<512, 2><<<dim3(2, NROWX / 128), 256, SMEM_TOTAL>>>(nullptr, nullptr); // Y = x @ W1a
    edge_kernel<<<N_REC, 256>>>(edge_attr, idx_send, We1, be1);
    gemm_hmma<256, 3><<<dim3(2, N_REC / 128), 256, SMEM_TOTAL>>>(bl1, nullptr);     // H -> gelu -> Amid
    gemm_hmma<256, 0><<<dim3(2, MTOT / 128), 256, SMEM_TOTAL>>>(bl2, out);          // out
}